// round 1
// baseline (speedup 1.0000x reference)
#include <cuda_runtime.h>
#include <math.h>

// Problem constants (shapes are fixed by the dataset; runtime sizes are
// taken from in_sizes but bounded by these).
#define MAXN 20000
#define MAXE 640000
#define MAXT (MAXE + MAXN)
#define NBATCH 8
#define FEAT 704            // 11 * 64 features per node
#define FEAT4 176           // FEAT / 4

// ---------------- scratch (static device allocations; no cudaMalloc) -------
__device__ int    g_deg[MAXN];
__device__ float  g_dinv[MAXN];
__device__ int    g_rowptr[MAXN + 1];
__device__ int    g_cursor[MAXN];
__device__ int2   g_edges[MAXT];           // (src, weight-bits), CSR by dest
__device__ float4 g_H1a[MAXN * 16];        // level-1 ping
__device__ float4 g_H1b[MAXN * 16];        // level-1 pong
__device__ float4 g_snap1[MAXN * 16];      // level-1 snapshot (h at last pow2)
__device__ float4 g_H2a[MAXN * 64];        // S1 = level-2 h0   (N x 256)
__device__ float4 g_H2b[MAXN * 64];        // level-2 ping
__device__ float4 g_H2c[MAXN * 64];        // level-2 pong
__device__ float4 g_snap2[MAXN * 48];      // level-2 snapshot, bands 0..2
__device__ float4 g_feats[MAXN * 176];     // per-node feature vector (N x 704)
__device__ int    g_start[NBATCH + 1];     // batch segment offsets
__device__ double g_acc[4 * NBATCH * FEAT];// raw moment sums

// ---------------- setup kernels --------------------------------------------
__global__ void k_init(int n) {
    int i = blockIdx.x * blockDim.x + threadIdx.x;
    if (i < n) { g_deg[i] = 1; g_cursor[i] = 0; }          // deg incl. self-loop
    if (i < 4 * NBATCH * FEAT) g_acc[i] = 0.0;
}

__global__ void k_count(const int* __restrict__ col, int e) {
    int i = blockIdx.x * blockDim.x + threadIdx.x;
    if (i < e) atomicAdd(&g_deg[col[i]], 1);
}

__global__ void k_dinv(int n) {
    int i = blockIdx.x * blockDim.x + threadIdx.x;
    if (i < n) g_dinv[i] = rsqrtf((float)g_deg[i]);
}

// single-block inclusive scan of g_deg -> g_rowptr
__global__ void k_scan(int n) {
    __shared__ int sh[1024];
    __shared__ int carry;
    if (threadIdx.x == 0) { carry = 0; g_rowptr[0] = 0; }
    __syncthreads();
    for (int base = 0; base < n; base += 1024) {
        int i = base + threadIdx.x;
        int v = (i < n) ? g_deg[i] : 0;
        sh[threadIdx.x] = v;
        __syncthreads();
        for (int off = 1; off < 1024; off <<= 1) {
            int t = (threadIdx.x >= off) ? sh[threadIdx.x - off] : 0;
            __syncthreads();
            sh[threadIdx.x] += t;
            __syncthreads();
        }
        if (i < n) g_rowptr[i + 1] = carry + sh[threadIdx.x];
        __syncthreads();
        if (threadIdx.x == 0) carry += sh[1023];
        __syncthreads();
    }
}

// scatter edges (and self loops) into CSR-by-destination with weights
__global__ void k_fill(const int* __restrict__ row, const int* __restrict__ col,
                       int e, int n) {
    int i = blockIdx.x * blockDim.x + threadIdx.x;
    if (i >= e + n) return;
    int r, c; float w;
    if (i < e) {
        r = row[i]; c = col[i];
        w = g_dinv[r] * g_dinv[c];
    } else {
        r = c = i - e;
        float d = g_dinv[r];
        w = d * d;
    }
    int pos = g_rowptr[c] + atomicAdd(&g_cursor[c], 1);
    g_edges[pos] = make_int2(r, __float_as_int(w));
}

// copy x into feats column block k=0
__global__ void k_xcopy(const float4* __restrict__ x, int n) {
    int i = blockIdx.x * blockDim.x + threadIdx.x;
    if (i >= n * 16) return;
    g_feats[(i >> 4) * FEAT4 + (i & 15)] = x[i];
}

// ---------------- level-1 cascade step (F = 64) ----------------------------
// mode 0: plain step.  mode 1: also save snapshot (t==1).
// mode 2: emit wavelet band |h - snap| into H2a & feats, refresh snapshot.
__global__ void k_step64(const float4* __restrict__ Hin, float4* __restrict__ Hout,
                         int n, int mode, int band) {
    int v = blockIdx.x * blockDim.y + threadIdx.y;
    if (v >= n) return;
    int tx = threadIdx.x;                  // 0..15 (float4 over 64 ch)
    int beg = g_rowptr[v], end = g_rowptr[v + 1];
    float4 acc = make_float4(0.f, 0.f, 0.f, 0.f);
    int e = beg;
    for (; e + 1 < end; e += 2) {
        int2 e0 = g_edges[e], e1 = g_edges[e + 1];
        float w0 = __int_as_float(e0.y), w1 = __int_as_float(e1.y);
        float4 h0 = Hin[e0.x * 16 + tx];
        float4 h1 = Hin[e1.x * 16 + tx];
        acc.x += w0 * h0.x; acc.y += w0 * h0.y; acc.z += w0 * h0.z; acc.w += w0 * h0.w;
        acc.x += w1 * h1.x; acc.y += w1 * h1.y; acc.z += w1 * h1.z; acc.w += w1 * h1.w;
    }
    if (e < end) {
        int2 e0 = g_edges[e];
        float w0 = __int_as_float(e0.y);
        float4 h0 = Hin[e0.x * 16 + tx];
        acc.x += w0 * h0.x; acc.y += w0 * h0.y; acc.z += w0 * h0.z; acc.w += w0 * h0.w;
    }
    float4 hv = Hin[v * 16 + tx];
    float4 o = make_float4(0.5f * (hv.x + acc.x), 0.5f * (hv.y + acc.y),
                           0.5f * (hv.z + acc.z), 0.5f * (hv.w + acc.w));
    Hout[v * 16 + tx] = o;
    if (mode == 1) {
        g_snap1[v * 16 + tx] = o;
    } else if (mode == 2) {
        float4 p = g_snap1[v * 16 + tx];
        float4 d = make_float4(fabsf(o.x - p.x), fabsf(o.y - p.y),
                               fabsf(o.z - p.z), fabsf(o.w - p.w));
        g_H2a[v * 64 + band * 16 + tx] = d;                    // S1 (level-2 h0)
        g_feats[v * FEAT4 + (1 + band) * 16 + tx] = d;         // feats k=1..4
        g_snap1[v * 16 + tx] = o;
    }
}

// ---------------- level-2 cascade step (F = 256) ---------------------------
// mode 0: plain. mode 1: save snapshot bands 0..2 (t==2).
// mode 2: emit nb bands (|h-snap|) starting at feats column 5+jbase; save
//         snapshot again if save!=0.
__global__ void k_step256(const float4* __restrict__ Hin, float4* __restrict__ Hout,
                          int n, int mode, int nb, int jbase, int save) {
    int v = blockIdx.x * blockDim.y + threadIdx.y;
    if (v >= n) return;
    int tx = threadIdx.x;                  // 0..63 (float4 over 256)
    int beg = g_rowptr[v], end = g_rowptr[v + 1];
    float4 acc = make_float4(0.f, 0.f, 0.f, 0.f);
    int e = beg;
    for (; e + 1 < end; e += 2) {
        int2 e0 = g_edges[e], e1 = g_edges[e + 1];
        float w0 = __int_as_float(e0.y), w1 = __int_as_float(e1.y);
        float4 h0 = Hin[e0.x * 64 + tx];
        float4 h1 = Hin[e1.x * 64 + tx];
        acc.x += w0 * h0.x; acc.y += w0 * h0.y; acc.z += w0 * h0.z; acc.w += w0 * h0.w;
        acc.x += w1 * h1.x; acc.y += w1 * h1.y; acc.z += w1 * h1.z; acc.w += w1 * h1.w;
    }
    if (e < end) {
        int2 e0 = g_edges[e];
        float w0 = __int_as_float(e0.y);
        float4 h0 = Hin[e0.x * 64 + tx];
        acc.x += w0 * h0.x; acc.y += w0 * h0.y; acc.z += w0 * h0.z; acc.w += w0 * h0.w;
    }
    float4 hv = Hin[v * 64 + tx];
    float4 o = make_float4(0.5f * (hv.x + acc.x), 0.5f * (hv.y + acc.y),
                           0.5f * (hv.z + acc.z), 0.5f * (hv.w + acc.w));
    Hout[v * 64 + tx] = o;
    if (mode == 2 && tx < nb * 16) {
        float4 p = g_snap2[v * 48 + tx];
        float4 d = make_float4(fabsf(o.x - p.x), fabsf(o.y - p.y),
                               fabsf(o.z - p.z), fabsf(o.w - p.w));
        int j = jbase + (tx >> 4);                              // 2nd-order index
        g_feats[v * FEAT4 + (5 + j) * 16 + (tx & 15)] = d;
    }
    if ((mode == 1 || (mode == 2 && save)) && tx < 48)
        g_snap2[v * 48 + tx] = o;
}

// ---------------- batch segments -------------------------------------------
__global__ void k_batchoff(const int* __restrict__ batch, int n) {
    int i = blockIdx.x * blockDim.x + threadIdx.x;
    if (i >= n) return;
    int b = batch[i];
    int pb = (i == 0) ? -1 : batch[i - 1];
    for (int k = pb + 1; k <= b; ++k) g_start[k] = i;
    if (i == n - 1)
        for (int k = b + 1; k <= NBATCH; ++k) g_start[k] = n;
}

// ---------------- raw moments (fp32 partials, fp64 merge) ------------------
#define MSLICE 32
__global__ void k_moments() {
    int f = blockIdx.x * blockDim.x + threadIdx.x;
    if (f >= FEAT) return;
    int b = blockIdx.y;
    int sl = blockIdx.z;
    int s = g_start[b], t = g_start[b + 1];
    int len = t - s;
    int i0 = s + (int)((long long)len * sl / MSLICE);
    int i1 = s + (int)((long long)len * (sl + 1) / MSLICE);
    if (i0 >= i1) return;
    const float* feats = (const float*)g_feats;
    float s1 = 0.f, s2 = 0.f, s3 = 0.f, s4 = 0.f;
    for (int i = i0; i < i1; ++i) {
        float v = feats[(size_t)i * FEAT + f];
        float v2 = v * v;
        s1 += v; s2 += v2; s3 += v2 * v; s4 += v2 * v2;
    }
    atomicAdd(&g_acc[(0 * NBATCH + b) * FEAT + f], (double)s1);
    atomicAdd(&g_acc[(1 * NBATCH + b) * FEAT + f], (double)s2);
    atomicAdd(&g_acc[(2 * NBATCH + b) * FEAT + f], (double)s3);
    atomicAdd(&g_acc[(3 * NBATCH + b) * FEAT + f], (double)s4);
}

__global__ void k_finalize(const float* __restrict__ wav, float* __restrict__ out,
                           int out_size) {
    int idx = blockIdx.x * blockDim.x + threadIdx.x;
    if (idx < NBATCH * FEAT) {
        int b = idx / FEAT, f = idx % FEAT;
        int c = g_start[b + 1] - g_start[b];
        double cnt = (c > 0) ? (double)c : 1.0;
        double m  = g_acc[(0 * NBATCH + b) * FEAT + f] / cnt;
        double e2 = g_acc[(1 * NBATCH + b) * FEAT + f] / cnt;
        double e3 = g_acc[(2 * NBATCH + b) * FEAT + f] / cnt;
        double e4 = g_acc[(3 * NBATCH + b) * FEAT + f] / cnt;
        double var = e2 - m * m;
        double m3 = e3 - 3.0 * m * e2 + 2.0 * m * m * m;
        double m4 = e4 - 4.0 * m * e3 + 6.0 * m * m * e2 - 3.0 * m * m * m * m;
        float skew, kurt;
        if (var > 0.0) {
            skew = (float)(m3 / (var * sqrt(var)));
            kurt = (float)(m4 / (var * var));
        } else { skew = 0.f; kurt = -3.f; }
        float* row = out + (size_t)b * (4 * FEAT);
        row[f] = (float)m;
        row[FEAT + f] = (float)var;
        row[2 * FEAT + f] = skew;
        row[3 * FEAT + f] = kurt;
    } else {
        int t = idx - NBATCH * FEAT;
        if (t < 68 && out_size >= NBATCH * 4 * FEAT + 68)
            out[NBATCH * 4 * FEAT + t] = wav[t];
    }
}

// ---------------- driver -----------------------------------------------------
extern "C" void kernel_launch(void* const* d_in, const int* in_sizes, int n_in,
                              void* d_out, int out_size) {
    const float* x   = (const float*)d_in[0];
    const int*   ei  = (const int*)d_in[1];
    const int*   bat = (const int*)d_in[2];
    const float* wav = (const float*)d_in[3];
    float* out = (float*)d_out;

    int E = in_sizes[1] / 2;
    int N = in_sizes[2];
    if (N > MAXN) N = MAXN;
    if (E > MAXE) E = MAXE;
    const int* row = ei;
    const int* col = ei + E;

    // resolve scratch addresses (host-side, not part of the captured graph)
    void *pH1a, *pH1b, *pH2a, *pH2b, *pH2c;
    cudaGetSymbolAddress(&pH1a, g_H1a);
    cudaGetSymbolAddress(&pH1b, g_H1b);
    cudaGetSymbolAddress(&pH2a, g_H2a);
    cudaGetSymbolAddress(&pH2b, g_H2b);
    cudaGetSymbolAddress(&pH2c, g_H2c);
    float4* H1a = (float4*)pH1a; float4* H1b = (float4*)pH1b;
    float4* H2a = (float4*)pH2a; float4* H2b = (float4*)pH2b; float4* H2c = (float4*)pH2c;

    // --- graph setup ---
    int initN = (N > 4 * NBATCH * FEAT) ? N : 4 * NBATCH * FEAT;
    k_init<<<(initN + 255) / 256, 256>>>(N);
    k_count<<<(E + 255) / 256, 256>>>(col, E);
    k_dinv<<<(N + 255) / 256, 256>>>(N);
    k_scan<<<1, 1024>>>(N);
    k_fill<<<(E + N + 255) / 256, 256>>>(row, col, E, N);
    k_xcopy<<<(N * 16 + 255) / 256, 256>>>((const float4*)x, N);

    // --- level-1 cascade: 16 steps, F=64 ---
    dim3 b64(16, 8);
    int g64 = (N + 7) / 8;
    for (int t = 1; t <= 16; ++t) {
        const float4* in = (t == 1) ? (const float4*)x : ((t & 1) ? H1b : H1a);
        float4* outp = (t & 1) ? H1a : H1b;
        int mode = 0, band = 0;
        if (t == 1) mode = 1;
        else if (t == 2)  { mode = 2; band = 0; }
        else if (t == 4)  { mode = 2; band = 1; }
        else if (t == 8)  { mode = 2; band = 2; }
        else if (t == 16) { mode = 2; band = 3; }
        k_step64<<<g64, b64>>>(in, outp, N, mode, band);
    }

    // --- level-2 cascade: 16 steps, F=256 ---
    dim3 b256(64, 4);
    int g256 = (N + 3) / 4;
    for (int t = 1; t <= 16; ++t) {
        const float4* in = (t == 1) ? (const float4*)H2a : ((t & 1) ? H2c : H2b);
        float4* outp = (t & 1) ? H2b : H2c;
        int mode = 0, nb = 0, jbase = 0, save = 0;
        if (t == 2)  { mode = 1; }
        else if (t == 4)  { mode = 2; nb = 1; jbase = 0; save = 1; }
        else if (t == 8)  { mode = 2; nb = 2; jbase = 1; save = 1; }
        else if (t == 16) { mode = 2; nb = 3; jbase = 3; save = 0; }
        k_step256<<<g256, b256>>>(in, outp, N, mode, nb, jbase, save);
    }

    // --- batch statistics ---
    k_batchoff<<<(N + 255) / 256, 256>>>(bat, N);
    dim3 mg((FEAT + 127) / 128, NBATCH, MSLICE);
    k_moments<<<mg, 128>>>();
    int fin = NBATCH * FEAT + 68;
    k_finalize<<<(fin + 255) / 256, 256>>>(wav, out, out_size);
}

// round 2
// speedup vs baseline: 1.3817x; 1.3817x over previous
#include <cuda_runtime.h>
#include <cuda_fp16.h>
#include <math.h>

#define MAXN 20000
#define MAXE 640000
#define MAXT (MAXE + MAXN)
#define NBATCH 8
#define FEAT 704            // 11 * 64 features per node
#define FEAT4 176           // FEAT / 4

// ---------------- scratch (static device allocations; no cudaMalloc) -------
__device__ int    g_deg[MAXN];
__device__ float  g_dinv[MAXN];
__device__ int    g_rowptr[MAXN + 1];
__device__ int    g_cursor[MAXN];
__device__ int2   g_edges[MAXT];           // (src, weight-bits), CSR by dest

// fp32 state (self path / diffs) + fp16 gather mirrors
__device__ float4 g_H1a[MAXN * 16];
__device__ float4 g_H1b[MAXN * 16];
__device__ float4 g_snap1[MAXN * 16];
__device__ uint2  g_xh[MAXN * 16];         // fp16 mirror of x
__device__ uint2  g_H1h0[MAXN * 16];       // fp16 mirror ping
__device__ uint2  g_H1h1[MAXN * 16];       // fp16 mirror pong

__device__ float4 g_H2a[MAXN * 64];        // S1 (level-2 h0, fp32)
__device__ float4 g_H2b[MAXN * 64];
__device__ float4 g_H2c[MAXN * 64];
__device__ uint2  g_H2h0[MAXN * 64];       // fp16 mirror of S1
__device__ uint2  g_H2h1[MAXN * 64];       // fp16 mirror ping
__device__ uint2  g_H2h2[MAXN * 64];       // fp16 mirror pong
__device__ float4 g_snap2[MAXN * 48];

__device__ float4 g_feats[MAXN * 176];     // per-node features (N x 704)
__device__ int    g_start[NBATCH + 1];
__device__ double g_acc[4 * NBATCH * FEAT];

// ---------------- fp16 pack helpers ----------------------------------------
__device__ __forceinline__ float4 h4_to_f4(uint2 p) {
    __half2 a = *reinterpret_cast<__half2*>(&p.x);
    __half2 b = *reinterpret_cast<__half2*>(&p.y);
    float2 fa = __half22float2(a), fb = __half22float2(b);
    return make_float4(fa.x, fa.y, fb.x, fb.y);
}
__device__ __forceinline__ uint2 f4_to_h4(float4 v) {
    __half2 a = __floats2half2_rn(v.x, v.y);
    __half2 b = __floats2half2_rn(v.z, v.w);
    uint2 p;
    p.x = *reinterpret_cast<unsigned*>(&a);
    p.y = *reinterpret_cast<unsigned*>(&b);
    return p;
}

// ---------------- setup kernels --------------------------------------------
__global__ void k_init(int n) {
    int i = blockIdx.x * blockDim.x + threadIdx.x;
    if (i < n) { g_deg[i] = 1; g_cursor[i] = 0; }          // deg incl. self-loop
    if (i < 4 * NBATCH * FEAT) g_acc[i] = 0.0;
}

__global__ void k_count(const int* __restrict__ col, int e) {
    int i = blockIdx.x * blockDim.x + threadIdx.x;
    if (i < e) atomicAdd(&g_deg[col[i]], 1);
}

__global__ void k_dinv(int n) {
    int i = blockIdx.x * blockDim.x + threadIdx.x;
    if (i < n) g_dinv[i] = rsqrtf((float)g_deg[i]);
}

// work-efficient single-block exclusive scan: 20 elems/thread + shuffle scan
__global__ void k_scan(int n) {
    const int T = 1024;
    int chunk = (n + T - 1) / T;                // <= 20 for N<=20000
    int t0 = threadIdx.x * chunk;
    int local[32];
    int s = 0;
    for (int j = 0; j < chunk; ++j) {
        int i = t0 + j;
        int v = (i < n) ? g_deg[i] : 0;
        local[j] = s;
        s += v;
    }
    int lane = threadIdx.x & 31, wid = threadIdx.x >> 5;
    int inc = s;
    #pragma unroll
    for (int o = 1; o < 32; o <<= 1) {
        int u = __shfl_up_sync(0xffffffffu, inc, o);
        if (lane >= o) inc += u;
    }
    __shared__ int wsum[32];
    if (lane == 31) wsum[wid] = inc;
    __syncthreads();
    if (wid == 0) {
        int w = wsum[lane];
        int wi = w;
        #pragma unroll
        for (int o = 1; o < 32; o <<= 1) {
            int u = __shfl_up_sync(0xffffffffu, wi, o);
            if (lane >= o) wi += u;
        }
        wsum[lane] = wi - w;                    // exclusive warp offset
    }
    __syncthreads();
    int exc = inc - s + wsum[wid];              // exclusive prefix of this thread
    for (int j = 0; j < chunk; ++j) {
        int i = t0 + j;
        if (i < n) g_rowptr[i] = exc + local[j];
    }
    if (threadIdx.x == T - 1) g_rowptr[n] = exc + s;
}

// scatter edges (and self loops) into CSR-by-destination with weights
__global__ void k_fill(const int* __restrict__ row, const int* __restrict__ col,
                       int e, int n) {
    int i = blockIdx.x * blockDim.x + threadIdx.x;
    if (i >= e + n) return;
    int r, c; float w;
    if (i < e) {
        r = row[i]; c = col[i];
        w = g_dinv[r] * g_dinv[c];
    } else {
        r = c = i - e;
        float d = g_dinv[r];
        w = d * d;
    }
    int pos = g_rowptr[c] + atomicAdd(&g_cursor[c], 1);
    g_edges[pos] = make_int2(r, __float_as_int(w));
}

// copy x into feats column block k=0 and build fp16 mirror
__global__ void k_xcopy(const float4* __restrict__ x, int n) {
    int i = blockIdx.x * blockDim.x + threadIdx.x;
    if (i >= n * 16) return;
    float4 v = x[i];
    g_feats[(i >> 4) * FEAT4 + (i & 15)] = v;
    g_xh[i] = f4_to_h4(v);
}

// ---------------- level-1 cascade step (F = 64) ----------------------------
// gather from fp16 mirror Hh; self/diff path in fp32 (Hs -> Hout); write both.
// mode 0: plain. mode 1: save snapshot (t==1). mode 2: emit band, refresh snap.
__global__ void k_step64(const uint2* __restrict__ Hh, const float4* __restrict__ Hs,
                         float4* __restrict__ Hout, uint2* __restrict__ Hhout,
                         int n, int mode, int band) {
    int v = blockIdx.x * blockDim.y + threadIdx.y;
    if (v >= n) return;
    int tx = threadIdx.x;                  // 0..15 (4 channels each)
    int beg = g_rowptr[v], end = g_rowptr[v + 1];
    float4 acc = make_float4(0.f, 0.f, 0.f, 0.f);
    int e = beg;
    for (; e + 1 < end; e += 2) {
        int2 e0 = g_edges[e], e1 = g_edges[e + 1];
        float w0 = __int_as_float(e0.y), w1 = __int_as_float(e1.y);
        float4 h0 = h4_to_f4(Hh[e0.x * 16 + tx]);
        float4 h1 = h4_to_f4(Hh[e1.x * 16 + tx]);
        acc.x += w0 * h0.x; acc.y += w0 * h0.y; acc.z += w0 * h0.z; acc.w += w0 * h0.w;
        acc.x += w1 * h1.x; acc.y += w1 * h1.y; acc.z += w1 * h1.z; acc.w += w1 * h1.w;
    }
    if (e < end) {
        int2 e0 = g_edges[e];
        float w0 = __int_as_float(e0.y);
        float4 h0 = h4_to_f4(Hh[e0.x * 16 + tx]);
        acc.x += w0 * h0.x; acc.y += w0 * h0.y; acc.z += w0 * h0.z; acc.w += w0 * h0.w;
    }
    float4 hv = Hs[v * 16 + tx];
    float4 o = make_float4(0.5f * (hv.x + acc.x), 0.5f * (hv.y + acc.y),
                           0.5f * (hv.z + acc.z), 0.5f * (hv.w + acc.w));
    Hout[v * 16 + tx] = o;
    Hhout[v * 16 + tx] = f4_to_h4(o);
    if (mode == 1) {
        g_snap1[v * 16 + tx] = o;
    } else if (mode == 2) {
        float4 p = g_snap1[v * 16 + tx];
        float4 d = make_float4(fabsf(o.x - p.x), fabsf(o.y - p.y),
                               fabsf(o.z - p.z), fabsf(o.w - p.w));
        g_H2a[v * 64 + band * 16 + tx] = d;                    // S1 fp32
        g_H2h0[v * 64 + band * 16 + tx] = f4_to_h4(d);         // S1 fp16 mirror
        g_feats[v * FEAT4 + (1 + band) * 16 + tx] = d;         // feats k=1..4
        g_snap1[v * 16 + tx] = o;
    }
}

// ---------------- level-2 cascade step (F = 256) ---------------------------
__global__ void k_step256(const uint2* __restrict__ Hh, const float4* __restrict__ Hs,
                          float4* __restrict__ Hout, uint2* __restrict__ Hhout,
                          int n, int mode, int nb, int jbase, int save) {
    int v = blockIdx.x * blockDim.y + threadIdx.y;
    if (v >= n) return;
    int tx = threadIdx.x;                  // 0..63 (4 channels each)
    int beg = g_rowptr[v], end = g_rowptr[v + 1];
    float4 acc = make_float4(0.f, 0.f, 0.f, 0.f);
    int e = beg;
    for (; e + 1 < end; e += 2) {
        int2 e0 = g_edges[e], e1 = g_edges[e + 1];
        float w0 = __int_as_float(e0.y), w1 = __int_as_float(e1.y);
        float4 h0 = h4_to_f4(Hh[e0.x * 64 + tx]);
        float4 h1 = h4_to_f4(Hh[e1.x * 64 + tx]);
        acc.x += w0 * h0.x; acc.y += w0 * h0.y; acc.z += w0 * h0.z; acc.w += w0 * h0.w;
        acc.x += w1 * h1.x; acc.y += w1 * h1.y; acc.z += w1 * h1.z; acc.w += w1 * h1.w;
    }
    if (e < end) {
        int2 e0 = g_edges[e];
        float w0 = __int_as_float(e0.y);
        float4 h0 = h4_to_f4(Hh[e0.x * 64 + tx]);
        acc.x += w0 * h0.x; acc.y += w0 * h0.y; acc.z += w0 * h0.z; acc.w += w0 * h0.w;
    }
    float4 hv = Hs[v * 64 + tx];
    float4 o = make_float4(0.5f * (hv.x + acc.x), 0.5f * (hv.y + acc.y),
                           0.5f * (hv.z + acc.z), 0.5f * (hv.w + acc.w));
    Hout[v * 64 + tx] = o;
    Hhout[v * 64 + tx] = f4_to_h4(o);
    if (mode == 2 && tx < nb * 16) {
        float4 p = g_snap2[v * 48 + tx];
        float4 d = make_float4(fabsf(o.x - p.x), fabsf(o.y - p.y),
                               fabsf(o.z - p.z), fabsf(o.w - p.w));
        int j = jbase + (tx >> 4);
        g_feats[v * FEAT4 + (5 + j) * 16 + (tx & 15)] = d;
    }
    if ((mode == 1 || (mode == 2 && save)) && tx < 48)
        g_snap2[v * 48 + tx] = o;
}

// ---------------- batch segments -------------------------------------------
__global__ void k_batchoff(const int* __restrict__ batch, int n) {
    int i = blockIdx.x * blockDim.x + threadIdx.x;
    if (i >= n) return;
    int b = batch[i];
    int pb = (i == 0) ? -1 : batch[i - 1];
    for (int k = pb + 1; k <= b; ++k) g_start[k] = i;
    if (i == n - 1)
        for (int k = b + 1; k <= NBATCH; ++k) g_start[k] = n;
}

// ---------------- raw moments (fp32 partials, fp64 merge) ------------------
#define MSLICE 32
__global__ void k_moments() {
    int f = blockIdx.x * blockDim.x + threadIdx.x;
    if (f >= FEAT) return;
    int b = blockIdx.y;
    int sl = blockIdx.z;
    int s = g_start[b], t = g_start[b + 1];
    int len = t - s;
    int i0 = s + (int)((long long)len * sl / MSLICE);
    int i1 = s + (int)((long long)len * (sl + 1) / MSLICE);
    if (i0 >= i1) return;
    const float* feats = (const float*)g_feats;
    float s1 = 0.f, s2 = 0.f, s3 = 0.f, s4 = 0.f;
    for (int i = i0; i < i1; ++i) {
        float v = feats[(size_t)i * FEAT + f];
        float v2 = v * v;
        s1 += v; s2 += v2; s3 += v2 * v; s4 += v2 * v2;
    }
    atomicAdd(&g_acc[(0 * NBATCH + b) * FEAT + f], (double)s1);
    atomicAdd(&g_acc[(1 * NBATCH + b) * FEAT + f], (double)s2);
    atomicAdd(&g_acc[(2 * NBATCH + b) * FEAT + f], (double)s3);
    atomicAdd(&g_acc[(3 * NBATCH + b) * FEAT + f], (double)s4);
}

__global__ void k_finalize(const float* __restrict__ wav, float* __restrict__ out,
                           int out_size) {
    int idx = blockIdx.x * blockDim.x + threadIdx.x;
    if (idx < NBATCH * FEAT) {
        int b = idx / FEAT, f = idx % FEAT;
        int c = g_start[b + 1] - g_start[b];
        double cnt = (c > 0) ? (double)c : 1.0;
        double m  = g_acc[(0 * NBATCH + b) * FEAT + f] / cnt;
        double e2 = g_acc[(1 * NBATCH + b) * FEAT + f] / cnt;
        double e3 = g_acc[(2 * NBATCH + b) * FEAT + f] / cnt;
        double e4 = g_acc[(3 * NBATCH + b) * FEAT + f] / cnt;
        double var = e2 - m * m;
        double m3 = e3 - 3.0 * m * e2 + 2.0 * m * m * m;
        double m4 = e4 - 4.0 * m * e3 + 6.0 * m * m * e2 - 3.0 * m * m * m * m;
        float skew, kurt;
        if (var > 0.0) {
            skew = (float)(m3 / (var * sqrt(var)));
            kurt = (float)(m4 / (var * var));
        } else { skew = 0.f; kurt = -3.f; }
        float* row = out + (size_t)b * (4 * FEAT);
        row[f] = (float)m;
        row[FEAT + f] = (float)var;
        row[2 * FEAT + f] = skew;
        row[3 * FEAT + f] = kurt;
    } else {
        int t = idx - NBATCH * FEAT;
        if (t < 68 && out_size >= NBATCH * 4 * FEAT + 68)
            out[NBATCH * 4 * FEAT + t] = wav[t];
    }
}

// ---------------- driver -----------------------------------------------------
extern "C" void kernel_launch(void* const* d_in, const int* in_sizes, int n_in,
                              void* d_out, int out_size) {
    const float* x   = (const float*)d_in[0];
    const int*   ei  = (const int*)d_in[1];
    const int*   bat = (const int*)d_in[2];
    const float* wav = (const float*)d_in[3];
    float* out = (float*)d_out;

    int E = in_sizes[1] / 2;
    int N = in_sizes[2];
    if (N > MAXN) N = MAXN;
    if (E > MAXE) E = MAXE;
    const int* row = ei;
    const int* col = ei + E;

    void *p;
    cudaGetSymbolAddress(&p, g_H1a);  float4* H1a = (float4*)p;
    cudaGetSymbolAddress(&p, g_H1b);  float4* H1b = (float4*)p;
    cudaGetSymbolAddress(&p, g_xh);   uint2*  Xh  = (uint2*)p;
    cudaGetSymbolAddress(&p, g_H1h0); uint2*  H1h0 = (uint2*)p;
    cudaGetSymbolAddress(&p, g_H1h1); uint2*  H1h1 = (uint2*)p;
    cudaGetSymbolAddress(&p, g_H2a);  float4* H2a = (float4*)p;
    cudaGetSymbolAddress(&p, g_H2b);  float4* H2b = (float4*)p;
    cudaGetSymbolAddress(&p, g_H2c);  float4* H2c = (float4*)p;
    cudaGetSymbolAddress(&p, g_H2h0); uint2*  H2h0 = (uint2*)p;
    cudaGetSymbolAddress(&p, g_H2h1); uint2*  H2h1 = (uint2*)p;
    cudaGetSymbolAddress(&p, g_H2h2); uint2*  H2h2 = (uint2*)p;

    // --- graph setup ---
    int initN = (N > 4 * NBATCH * FEAT) ? N : 4 * NBATCH * FEAT;
    k_init<<<(initN + 255) / 256, 256>>>(N);
    k_count<<<(E + 255) / 256, 256>>>(col, E);
    k_dinv<<<(N + 255) / 256, 256>>>(N);
    k_scan<<<1, 1024>>>(N);
    k_fill<<<(E + N + 255) / 256, 256>>>(row, col, E, N);
    k_xcopy<<<(N * 16 + 255) / 256, 256>>>((const float4*)x, N);

    // --- level-1 cascade: 16 steps, F=64 ---
    dim3 b64(16, 8);
    int g64 = (N + 7) / 8;
    for (int t = 1; t <= 16; ++t) {
        const uint2*  inh = (t == 1) ? Xh : ((t & 1) ? H1h1 : H1h0);
        const float4* ins = (t == 1) ? (const float4*)x : ((t & 1) ? H1b : H1a);
        float4* outs = (t & 1) ? H1a : H1b;
        uint2*  outh = (t & 1) ? H1h0 : H1h1;
        int mode = 0, band = 0;
        if (t == 1) mode = 1;
        else if (t == 2)  { mode = 2; band = 0; }
        else if (t == 4)  { mode = 2; band = 1; }
        else if (t == 8)  { mode = 2; band = 2; }
        else if (t == 16) { mode = 2; band = 3; }
        k_step64<<<g64, b64>>>(inh, ins, outs, outh, N, mode, band);
    }

    // --- level-2 cascade: 16 steps, F=256 ---
    dim3 b256(64, 4);
    int g256 = (N + 3) / 4;
    for (int t = 1; t <= 16; ++t) {
        const uint2*  inh = (t == 1) ? H2h0 : ((t & 1) ? H2h2 : H2h1);
        const float4* ins = (t == 1) ? (const float4*)H2a : ((t & 1) ? H2c : H2b);
        float4* outs = (t & 1) ? H2b : H2c;
        uint2*  outh = (t & 1) ? H2h1 : H2h2;
        int mode = 0, nb = 0, jbase = 0, save = 0;
        if (t == 2)  { mode = 1; }
        else if (t == 4)  { mode = 2; nb = 1; jbase = 0; save = 1; }
        else if (t == 8)  { mode = 2; nb = 2; jbase = 1; save = 1; }
        else if (t == 16) { mode = 2; nb = 3; jbase = 3; save = 0; }
        k_step256<<<g256, b256>>>(inh, ins, outs, outh, N, mode, nb, jbase, save);
    }

    // --- batch statistics ---
    k_batchoff<<<(N + 255) / 256, 256>>>(bat, N);
    dim3 mg((FEAT + 127) / 128, NBATCH, MSLICE);
    k_moments<<<mg, 128>>>();
    int fin = NBATCH * FEAT + 68;
    k_finalize<<<(fin + 255) / 256, 256>>>(wav, out, out_size);
}